// round 1
// baseline (speedup 1.0000x reference)
#include <cuda_runtime.h>
#include <cstdint>

// Problem constants
#define B_DIM   512
#define IN_DIM  65536
#define OUT_DIM 16384
#define K_DIM   32
#define OTILE   8

// 128 MB scratch for transposed x: xt[in][b]
__device__ float g_xt[(size_t)IN_DIM * B_DIM];

// ---------------------------------------------------------------------------
// Kernel 1: transpose x (B, IN) -> xt (IN, B). Tiled 32x32 via smem.
// ---------------------------------------------------------------------------
__global__ void transpose_kernel(const float* __restrict__ x) {
    __shared__ float tile[32][33];
    const int in0 = blockIdx.x * 32;   // along IN
    const int b0  = blockIdx.y * 32;   // along B
    const int tx  = threadIdx.x;       // 0..31
    const int ty  = threadIdx.y;       // 0..7

    // Coalesced read along IN
    #pragma unroll
    for (int i = ty; i < 32; i += 8) {
        tile[i][tx] = x[(size_t)(b0 + i) * IN_DIM + (in0 + tx)];
    }
    __syncthreads();

    // Coalesced write along B
    #pragma unroll
    for (int i = ty; i < 32; i += 8) {
        g_xt[(size_t)(in0 + i) * B_DIM + (b0 + tx)] = tile[tx][i];
    }
}

// ---------------------------------------------------------------------------
// Kernel 2: gather + dot. One block = OTILE outputs, 512 threads = batch rows.
// Each (o,k) column read is a contiguous 2KB load across the block.
// ---------------------------------------------------------------------------
__global__ __launch_bounds__(B_DIM) void sparse_linear_kernel(
    const int*   __restrict__ idx,
    const float* __restrict__ w,
    const float* __restrict__ bias,
    float*       __restrict__ out)
{
    const int o0  = blockIdx.x * OTILE;
    const int tid = threadIdx.x;   // = batch row b

    __shared__ int   sidx[OTILE][K_DIM];
    __shared__ float sw[OTILE][K_DIM];
    __shared__ float sbias[OTILE];
    __shared__ float sout[B_DIM][OTILE + 1];   // +1 pad: stride 9, gcd(9,32)=1

    // Stage indices / weights / bias
    if (tid < OTILE * K_DIM) {
        const int oo = tid / K_DIM;
        const int kk = tid % K_DIM;
        sidx[oo][kk] = idx[(size_t)(o0 + oo) * K_DIM + kk];
        sw[oo][kk]   = w[(size_t)(o0 + oo) * K_DIM + kk];
    }
    if (tid < OTILE) sbias[tid] = bias[o0 + tid];
    __syncthreads();

    // Accumulate: per output tile, 32 independent gathered loads batched up
    // front (ptxas front-batches the unrolled loads -> high MLP), then FMAs.
    #pragma unroll
    for (int oo = 0; oo < OTILE; oo++) {
        float acc = 0.0f;
        #pragma unroll
        for (int k = 0; k < K_DIM; k++) {
            const size_t col = (size_t)sidx[oo][k];
            acc += g_xt[col * B_DIM + tid] * sw[oo][k];
        }
        sout[tid][oo] = acc + sbias[oo];
    }
    __syncthreads();

    // Coalesced store: groups of 8 threads write 8 consecutive floats (32B
    // sector fully written) of out[b][o0:o0+8].
    #pragma unroll
    for (int i = tid; i < B_DIM * OTILE; i += B_DIM) {
        const int b  = i >> 3;
        const int oo = i & (OTILE - 1);
        out[(size_t)b * OUT_DIM + (o0 + oo)] = sout[b][oo];
    }
}

// ---------------------------------------------------------------------------
// Launch
// ---------------------------------------------------------------------------
extern "C" void kernel_launch(void* const* d_in, const int* in_sizes, int n_in,
                              void* d_out, int out_size) {
    const float* x    = (const float*)d_in[0];
    const int*   idx  = (const int*)  d_in[1];
    const float* w    = (const float*)d_in[2];
    const float* bias = (const float*)d_in[3];
    float*       out  = (float*)d_out;

    // Kernel 1: transpose x -> g_xt
    dim3 tb(32, 8);
    dim3 tg(IN_DIM / 32, B_DIM / 32);
    transpose_kernel<<<tg, tb>>>(x);

    // Kernel 2: gather + dot
    sparse_linear_kernel<<<OUT_DIM / OTILE, B_DIM>>>(idx, w, bias, out);
}

// round 2
// speedup vs baseline: 1.2506x; 1.2506x over previous
#include <cuda_runtime.h>
#include <cstdint>

// Problem constants
#define B_DIM   512
#define HALF_B  256
#define IN_DIM  65536
#define OUT_DIM 16384
#define K_DIM   32
#define OTILE   8

// 128 MB scratch for transposed x: xt[in][b]
__device__ float g_xt[(size_t)IN_DIM * B_DIM];

// ---------------------------------------------------------------------------
// Kernel 1: transpose x (B, IN) -> xt (IN, B). Tiled 32x32 via smem.
// ---------------------------------------------------------------------------
__global__ void transpose_kernel(const float* __restrict__ x) {
    __shared__ float tile[32][33];
    const int in0 = blockIdx.x * 32;   // along IN
    const int b0  = blockIdx.y * 32;   // along B
    const int tx  = threadIdx.x;       // 0..31
    const int ty  = threadIdx.y;       // 0..7

    #pragma unroll
    for (int i = ty; i < 32; i += 8) {
        tile[i][tx] = x[(size_t)(b0 + i) * IN_DIM + (in0 + tx)];
    }
    __syncthreads();

    #pragma unroll
    for (int i = ty; i < 32; i += 8) {
        g_xt[(size_t)(in0 + i) * B_DIM + (b0 + tx)] = tile[tx][i];
    }
}

// ---------------------------------------------------------------------------
// Kernel 2: gather + dot, processed in two B-halves so each half's xt slice
// (64 MB) stays L2-resident. Block = 8 outputs x 256 batch rows.
// 256 threads: q = tid&63 selects a b-quad (float4), g = tid>>6 handles
// outputs {g, g+4}. Every (o,k) column read is a contiguous 1KB block load.
// ---------------------------------------------------------------------------
__global__ __launch_bounds__(256) void sparse_linear_kernel(
    const int*   __restrict__ idx,
    const float* __restrict__ w,
    const float* __restrict__ bias,
    float*       __restrict__ out)
{
    const int o0   = blockIdx.x * OTILE;
    const int half = blockIdx.y;           // 0: b in [0,256), 1: b in [256,512)
    const int tid  = threadIdx.x;
    const int q    = tid & 63;             // b-quad within half
    const int g    = tid >> 6;             // 0..3

    __shared__ int   sidx[OTILE][K_DIM];
    __shared__ float sw[OTILE][K_DIM];
    __shared__ float sbias[OTILE];
    __shared__ float sout[HALF_B][12];     // row stride 12 floats: 16B-aligned,
                                           // conflict-free float4 read

    // Stage indices / weights / bias (OTILE*K = 256 = blockDim)
    {
        const int oo = tid >> 5;           // tid / K_DIM
        const int kk = tid & 31;
        sidx[oo][kk] = idx[(size_t)(o0 + oo) * K_DIM + kk];
        sw[oo][kk]   = w[(size_t)(o0 + oo) * K_DIM + kk];
        if (tid < OTILE) sbias[tid] = bias[o0 + tid];
    }
    __syncthreads();

    const float4* __restrict__ xt4 =
        reinterpret_cast<const float4*>(g_xt) + (size_t)half * 64 + q;

    #pragma unroll
    for (int p = 0; p < 2; p++) {
        const int oo = g + p * 4;
        float4 acc = make_float4(0.f, 0.f, 0.f, 0.f);
        #pragma unroll
        for (int k = 0; k < K_DIM; k++) {
            const size_t col = (size_t)sidx[oo][k];
            const float4 v = __ldg(&xt4[col * (B_DIM / 4)]);
            const float  wv = sw[oo][k];
            acc.x += v.x * wv;
            acc.y += v.y * wv;
            acc.z += v.z * wv;
            acc.w += v.w * wv;
        }
        const float bv = sbias[oo];
        sout[4 * q + 0][oo] = acc.x + bv;
        sout[4 * q + 1][oo] = acc.y + bv;
        sout[4 * q + 2][oo] = acc.z + bv;
        sout[4 * q + 3][oo] = acc.w + bv;
    }
    __syncthreads();

    // Store: thread t owns b = half*256 + t, writes out[b][o0..o0+7] as two
    // STG.128 -> each 32B sector of out written whole.
    {
        const int b = half * HALF_B + tid;
        float4* dst = reinterpret_cast<float4*>(out + (size_t)b * OUT_DIM + o0);
        const float4* src = reinterpret_cast<const float4*>(&sout[tid][0]);
        dst[0] = src[0];
        dst[1] = src[1];
    }
}

// ---------------------------------------------------------------------------
// Launch
// ---------------------------------------------------------------------------
extern "C" void kernel_launch(void* const* d_in, const int* in_sizes, int n_in,
                              void* d_out, int out_size) {
    const float* x    = (const float*)d_in[0];
    const int*   idx  = (const int*)  d_in[1];
    const float* w    = (const float*)d_in[2];
    const float* bias = (const float*)d_in[3];
    float*       out  = (float*)d_out;

    // Kernel 1: transpose x -> g_xt
    dim3 tb(32, 8);
    dim3 tg(IN_DIM / 32, B_DIM / 32);
    transpose_kernel<<<tg, tb>>>(x);

    // Kernel 2: gather + dot, half 0 scheduled before half 1 (y slow axis)
    dim3 gg(OUT_DIM / OTILE, 2);
    sparse_linear_kernel<<<gg, 256>>>(idx, w, bias, out);
}

// round 3
// speedup vs baseline: 1.5330x; 1.2258x over previous
#include <cuda_runtime.h>
#include <cstdint>

// Problem constants
#define B_DIM   512
#define HALF_B  256
#define IN_DIM  65536
#define OUT_DIM 16384
#define K_DIM   32
#define OTILE   8

// 128 MB scratch for transposed x: xt[in][b]
__device__ float g_xt[(size_t)IN_DIM * B_DIM];

// ---------------------------------------------------------------------------
// Kernel 1: transpose one b-half of x into xt. Vectorized float4 both ways.
// Tile: 32 b-rows x 128 in-cols. Block 256 threads.
// ---------------------------------------------------------------------------
__global__ __launch_bounds__(256) void transpose_half_kernel(
    const float* __restrict__ x, int half)
{
    __shared__ float4 tile4[32][33];           // [b_row][in_col/4], padded

    const int in0 = blockIdx.x * 128;
    const int b0  = half * HALF_B + blockIdx.y * 32;
    const int t   = threadIdx.x;

    // Load: float4 along IN. Warp reads 128B-contiguous per row.
    const int c4 = t & 31;                     // float4 column 0..31
    const int r0 = t >> 5;                     // 0..7
    #pragma unroll
    for (int it = 0; it < 4; it++) {
        const int r = r0 + 8 * it;             // b row 0..31
        tile4[r][c4] =
            *(const float4*)&x[(size_t)(b0 + r) * IN_DIM + in0 + 4 * c4];
    }
    __syncthreads();

    // Store: float4 along B. Warp writes contiguous 128B per in-row group.
    const int b4 = t & 7;                      // b-quad 0..7 (b = b0 + 4*b4..)
    const int i0 = t >> 3;                     // 0..31
    #pragma unroll
    for (int it = 0; it < 4; it++) {
        const int i = i0 + 32 * it;            // in_local 0..127
        const int c  = i >> 2;                 // tile4 column
        const int cc = i & 3;                  // component within float4
        float4 v;
        v.x = ((const float*)&tile4[4 * b4 + 0][c])[cc];
        v.y = ((const float*)&tile4[4 * b4 + 1][c])[cc];
        v.z = ((const float*)&tile4[4 * b4 + 2][c])[cc];
        v.w = ((const float*)&tile4[4 * b4 + 3][c])[cc];
        *(float4*)&g_xt[(size_t)(in0 + i) * B_DIM + b0 + 4 * b4] = v;
    }
}

// ---------------------------------------------------------------------------
// Kernel 2: gather + dot for one b-half (xt half is L2-hot from the
// immediately preceding transpose launch). Block = 8 outputs x 256 b-rows.
// ---------------------------------------------------------------------------
__global__ __launch_bounds__(256) void sparse_linear_kernel(
    const int*   __restrict__ idx,
    const float* __restrict__ w,
    const float* __restrict__ bias,
    float*       __restrict__ out,
    int half)
{
    const int o0  = blockIdx.x * OTILE;
    const int tid = threadIdx.x;
    const int q   = tid & 63;                  // b-quad within half
    const int g   = tid >> 6;                  // 0..3

    __shared__ int4   sidx4[OTILE][K_DIM / 4];
    __shared__ float4 sw4[OTILE][K_DIM / 4];
    __shared__ float  sbias[OTILE];
    __shared__ float  sout[HALF_B][12];        // stride 12: 16B-aligned rows

    // Stage indices / weights (vectorized) / bias
    if (tid < 64) {
        sidx4[tid >> 3][tid & 7] =
            ((const int4*)idx)[(size_t)(o0 + (tid >> 3)) * 8 + (tid & 7)];
    } else if (tid < 128) {
        const int u = tid - 64;
        sw4[u >> 3][u & 7] =
            ((const float4*)w)[(size_t)(o0 + (u >> 3)) * 8 + (u & 7)];
    } else if (tid < 128 + OTILE) {
        sbias[tid - 128] = bias[o0 + (tid - 128)];
    }
    __syncthreads();

    const float4* __restrict__ xt4 =
        reinterpret_cast<const float4*>(g_xt) + (size_t)half * 64 + q;

    #pragma unroll
    for (int p = 0; p < 2; p++) {
        const int oo = g + p * 4;
        float4 acc = make_float4(0.f, 0.f, 0.f, 0.f);
        #pragma unroll
        for (int k4 = 0; k4 < K_DIM / 4; k4++) {
            const int4   ii = sidx4[oo][k4];   // one LDS.128 broadcast
            const float4 ww = sw4[oo][k4];     // one LDS.128 broadcast
            const float4 v0 = __ldg(&xt4[(size_t)ii.x * (B_DIM / 4)]);
            const float4 v1 = __ldg(&xt4[(size_t)ii.y * (B_DIM / 4)]);
            const float4 v2 = __ldg(&xt4[(size_t)ii.z * (B_DIM / 4)]);
            const float4 v3 = __ldg(&xt4[(size_t)ii.w * (B_DIM / 4)]);
            acc.x += v0.x * ww.x; acc.y += v0.y * ww.x;
            acc.z += v0.z * ww.x; acc.w += v0.w * ww.x;
            acc.x += v1.x * ww.y; acc.y += v1.y * ww.y;
            acc.z += v1.z * ww.y; acc.w += v1.w * ww.y;
            acc.x += v2.x * ww.z; acc.y += v2.y * ww.z;
            acc.z += v2.z * ww.z; acc.w += v2.w * ww.z;
            acc.x += v3.x * ww.w; acc.y += v3.y * ww.w;
            acc.z += v3.z * ww.w; acc.w += v3.w * ww.w;
        }
        const float bv = sbias[oo];
        sout[4 * q + 0][oo] = acc.x + bv;
        sout[4 * q + 1][oo] = acc.y + bv;
        sout[4 * q + 2][oo] = acc.z + bv;
        sout[4 * q + 3][oo] = acc.w + bv;
    }
    __syncthreads();

    // Store: thread t owns b = half*256 + t, writes out[b][o0..o0+7] as two
    // STG.128 -> each 32B sector written whole.
    {
        const int b = half * HALF_B + tid;
        float4* dst = reinterpret_cast<float4*>(out + (size_t)b * OUT_DIM + o0);
        const float4* src = reinterpret_cast<const float4*>(&sout[tid][0]);
        dst[0] = src[0];
        dst[1] = src[1];
    }
}

// ---------------------------------------------------------------------------
// Launch: pipeline halves so each gather consumes an L2-hot xt half.
// ---------------------------------------------------------------------------
extern "C" void kernel_launch(void* const* d_in, const int* in_sizes, int n_in,
                              void* d_out, int out_size) {
    const float* x    = (const float*)d_in[0];
    const int*   idx  = (const int*)  d_in[1];
    const float* w    = (const float*)d_in[2];
    const float* bias = (const float*)d_in[3];
    float*       out  = (float*)d_out;

    dim3 tb(256);
    dim3 tg(IN_DIM / 128, HALF_B / 32);        // (512, 8) per half
    dim3 gg(OUT_DIM / OTILE);                  // 2048 per half

    transpose_half_kernel<<<tg, tb>>>(x, 0);
    sparse_linear_kernel<<<gg, 256>>>(idx, w, bias, out, 0);
    transpose_half_kernel<<<tg, tb>>>(x, 1);
    sparse_linear_kernel<<<gg, 256>>>(idx, w, bias, out, 1);
}